// round 11
// baseline (speedup 1.0000x reference)
#include <cuda_runtime.h>
#include <cuda_fp16.h>
#include <math.h>

// Fixed problem shape: B=16, H=W=512
#define Bn 16
#define Hn 512
#define Wn 512
#define TILE 32
#define FD  34          // feat rows/cols (halo 1)
#define FDPH 40         // feat pitch (halves)
#define ID  36          // input tile rows/cols (halo 2)
#define IDPH 44         // input pitch (halves) — covers B reads up to col 41
#define IN_PLANE (ID*IDPH)       // 1584 halves per channel
#define IN_HALVES (3*IN_PLANE)   // 4752
#define IN_REGION 4928           // + zero tail for padded-K reads
#define FEAT_HALVES (16*FD*FDPH) // 21760

#define SMEM_FLOATS ((IN_REGION + FEAT_HALVES)/2)   // 13344 floats = 53.4KB

typedef unsigned long long ull;

__device__ __forceinline__ ull pack2(float lo, float hi) {
    ull r; asm("mov.b64 %0, {%1, %2};" : "=l"(r) : "f"(lo), "f"(hi)); return r;
}
__device__ __forceinline__ void unpack2(ull v, float& lo, float& hi) {
    asm("mov.b64 {%0, %1}, %2;" : "=f"(lo), "=f"(hi) : "l"(v));
}
__device__ __forceinline__ void ffma2(ull& d, ull a, ull b) {
    asm("fma.rn.f32x2 %0, %1, %2, %0;" : "+l"(d) : "l"(a), "l"(b));
}
__device__ __forceinline__ ull fma2v(ull a, ull b, ull c) {
    ull r; asm("fma.rn.f32x2 %0, %1, %2, %3;" : "=l"(r) : "l"(a), "l"(b), "l"(c)); return r;
}
__device__ __forceinline__ ull mul2(ull a, ull b) {
    ull r; asm("mul.rn.f32x2 %0, %1, %2;" : "=l"(r) : "l"(a), "l"(b)); return r;
}

// GELU on 2 packed fp32 lanes: x * sigmoid(1.59577x + 0.0713548x^3)
__device__ __forceinline__ ull gelu2(ull x2) {
    ull xsq = mul2(x2, x2);
    ull t = fma2v(xsq, pack2(0.07135481627f, 0.07135481627f),
                        pack2(1.59576912161f, 1.59576912161f));
    ull y = mul2(x2, t);
    ull z = mul2(y, pack2(-1.44269504089f, -1.44269504089f));
    float zlo, zhi; unpack2(z, zlo, zhi);
    float elo, ehi;
    asm("ex2.approx.f32 %0, %1;" : "=f"(elo) : "f"(zlo));
    asm("ex2.approx.f32 %0, %1;" : "=f"(ehi) : "f"(zhi));
    float dlo = 1.0f + elo, dhi = 1.0f + ehi;
    float slo, shi;
    asm("rcp.approx.f32 %0, %1;" : "=f"(slo) : "f"(dlo));
    asm("rcp.approx.f32 %0, %1;" : "=f"(shi) : "f"(dhi));
    return mul2(x2, pack2(slo, shi));
}

__device__ __forceinline__ unsigned packh2(float lo, float hi) {
    __half2 h = __floats2half2_rn(lo, hi);
    return *(unsigned*)&h;
}

// W1 value at padded-K index k (k = c*4 + kx; kx==3 or k>=12 are zero pad)
__device__ __forceinline__ float w1_at(const float* __restrict__ w1,
                                       int och, int k, int ky) {
    int c = k >> 2, kx = k & 3;
    bool real = (kx < 3) && (k < 12);
    return real ? __ldg(&w1[och*27 + c*9 + ky*3 + kx]) : 0.f;
}

__global__ __launch_bounds__(256, 3)
void fused_residual_advection(const float* __restrict__ pm25,
                              const float* __restrict__ wind,
                              const float* __restrict__ topo,
                              const float* __restrict__ w1,
                              const float* __restrict__ b1,
                              const float* __restrict__ w2,
                              const float* __restrict__ b2,
                              const float* __restrict__ wk,
                              float* __restrict__ out)
{
    extern __shared__ float smem[];
    __half* s_in_h   = (__half*)smem;         // [IN_REGION] fp16 input + zero tail
    __half* s_feat_h = s_in_h + IN_REGION;    // [16][34][40] fp16 feat

    const int tid = threadIdx.x;
    const int b   = blockIdx.z;
    const int ty0 = blockIdx.y * TILE;
    const int tx0 = blockIdx.x * TILE;

    // ---- stage input as fp16 (zero-padded cols/rows + zero tail) ----
    const int gy0 = ty0 - 2, gx0 = tx0 - 2;
    const float* wind0 = wind + (size_t)b * 2 * Hn * Wn;
    const float* wind1 = wind0 + Hn * Wn;
    const float* topob = topo + (size_t)b * Hn * Wn;
    for (int i = tid; i < IN_REGION; i += 256) {
        int c   = i / IN_PLANE;            // 3 = zero tail
        int rem = i - c * IN_PLANE;
        int ly  = rem / IDPH;
        int lx  = rem - ly * IDPH;
        float v = 0.f;
        if (c < 3 && lx < ID) {
            int gy = gy0 + ly, gx = gx0 + lx;
            if ((unsigned)gy < Hn && (unsigned)gx < Wn) {
                const float* src = (c == 0) ? wind0 : ((c == 1) ? wind1 : topob);
                v = __ldg(src + (size_t)gy * Wn + gx);
            }
        }
        s_in_h[i] = __float2half_rn(v);
    }

    // ---- per-thread mma fragment setup ----
    const int lane = tid & 31;
    const int wrp  = tid >> 5;
    const int nof  = lane >> 2;   // A/C row group, B column
    const int kq   = lane & 3;    // k group

    // A fragments (W1 fp16, K padded to 16), one per ky
    unsigned afr[3][4];
    {
        const int k0 = 2*kq;
        #pragma unroll
        for (int ky = 0; ky < 3; ky++) {
            afr[ky][0] = packh2(w1_at(w1, nof,   k0,   ky), w1_at(w1, nof,   k0+1, ky));
            afr[ky][1] = packh2(w1_at(w1, nof+8, k0,   ky), w1_at(w1, nof+8, k0+1, ky));
            afr[ky][2] = packh2(w1_at(w1, nof,   k0+8, ky), w1_at(w1, nof,   k0+9, ky));
            afr[ky][3] = packh2(w1_at(w1, nof+8, k0+8, ky), w1_at(w1, nof+8, k0+9, ky));
        }
    }
    // B address prep: 4 half addresses per thread (k0,k0+1,k0+8,k0+9), column nof
    int rel[4], mulm[4];
    {
        const int ks[4] = {2*kq, 2*kq + 1, 2*kq + 8, 2*kq + 9};
        #pragma unroll
        for (int j = 0; j < 4; j++) {
            int k = ks[j], c = k >> 2, kx = k & 3;
            bool real = (kx < 3) && (k < 12);
            rel[j]  = real ? (c*IN_PLANE + nof + kx) : IN_HALVES;  // pad -> zero tail
            mulm[j] = real ? 1 : 0;
        }
    }
    const float bias0 = __ldg(&b1[nof]);
    const float bias1 = __ldg(&b1[nof + 8]);
    __syncthreads();

    // ---- phase 2: conv1 via mma.m16n8k16 + GELU -> fp16 feat ----
    // groups: 34 feat rows x 5 x-groups of 8 px (cols 32..39 masked to 0)
    {
        const unsigned short* s_in_u = (const unsigned short*)s_in_h;
        for (int g5 = wrp; g5 < 170; g5 += 8) {
            const int fy = g5 / 5;
            const int x0 = (g5 - fy*5) * 8;
            const int grp = fy*IDPH + x0;
            const int ad0 = rel[0] + grp*mulm[0];
            const int ad1 = rel[1] + grp*mulm[1];
            const int ad2 = rel[2] + grp*mulm[2];
            const int ad3 = rel[3] + grp*mulm[3];
            float d0 = bias0, d1 = bias0, d2 = bias1, d3 = bias1;
            #pragma unroll
            for (int ky = 0; ky < 3; ky++) {
                unsigned lo0 = s_in_u[ad0 + ky*IDPH];
                unsigned lo1 = s_in_u[ad1 + ky*IDPH];
                unsigned lo2 = s_in_u[ad2 + ky*IDPH];
                unsigned lo3 = s_in_u[ad3 + ky*IDPH];
                unsigned bb0 = lo0 | (lo1 << 16);
                unsigned bb1 = lo2 | (lo3 << 16);
                asm volatile(
                    "mma.sync.aligned.m16n8k16.row.col.f32.f16.f16.f32 "
                    "{%0,%1,%2,%3}, {%4,%5,%6,%7}, {%8,%9}, {%0,%1,%2,%3};"
                    : "+f"(d0), "+f"(d1), "+f"(d2), "+f"(d3)
                    : "r"(afr[ky][0]), "r"(afr[ky][1]), "r"(afr[ky][2]), "r"(afr[ky][3]),
                      "r"(bb0), "r"(bb1));
            }
            // epilogue: channels nof, nof+8; pixels (fy, fx0), (fy, fx0+1)
            const int fx0 = x0 + 2*kq;
            const bool okR = (unsigned)(ty0 - 1 + fy) < Hn;
            const bool ok0 = okR && ((unsigned)(tx0 - 1 + fx0) < Wn) && (fx0 < FD);
            const bool ok1 = okR && ((unsigned)(tx0 + fx0) < Wn) && (fx0 + 1 < FD);
            float g0, g1, g2, g3;
            unpack2(gelu2(pack2(d0, d1)), g0, g1);
            unpack2(gelu2(pack2(d2, d3)), g2, g3);
            const int po = fy*FDPH + fx0;
            *(__half2*)&s_feat_h[nof    *FD*FDPH + po] =
                __floats2half2_rn(ok0 ? g0 : 0.f, ok1 ? g1 : 0.f);
            *(__half2*)&s_feat_h[(nof+8)*FD*FDPH + po] =
                __floats2half2_rn(ok0 ? g2 : 0.f, ok1 ? g3 : 0.f);
        }
    }
    __syncthreads();

    // ---- phase 3: conv2 (active taps) + bilinear; f32x2 x-pairs, fp16 feat ----
    const int x0p = (tid & 7) * 4;
    const int row = tid >> 3;
    const float* img = pm25 + (size_t)b * Hn * Wn;
    float* s_wdup = smem;   // overlay on dead input region; 576 floats

    float acc[4] = {0.f, 0.f, 0.f, 0.f};

    for (int k = 0; k < 9; k++) {
        const float wkv = __ldg(&wk[k]);
        if (wkv == 0.0f) continue;          // uniform across block, value-exact
        const int kdy = k / 3 - 1, kdx = k - (k/3)*3 - 1;

        __syncthreads();
        for (int i = tid; i < 144; i += 256) {
            const int c = i / 9, j = i - c * 9;
            const float wy = __ldg(&w2[(size_t)(2*k)    *144 + c*9 + j]);
            const float wx = __ldg(&w2[(size_t)(2*k + 1)*144 + c*9 + j]);
            float* p = &s_wdup[(j*16 + c)*4];
            p[0] = wy; p[1] = wy; p[2] = wx; p[3] = wx;
        }
        __syncthreads();

        const float bdy = __ldg(&b2[2*k]), bdx = __ldg(&b2[2*k + 1]);
        ull ady0 = pack2(bdy, bdy), ady1 = ady0;
        ull adx0 = pack2(bdx, bdx), adx1 = adx0;

        #pragma unroll
        for (int c = 0; c < 16; c++) {
            const __half* fb = s_feat_h + c*FD*FDPH + row*FDPH + x0p;
            #pragma unroll
            for (int ky = 0; ky < 3; ky++) {
                const __half* rp = fb + ky*FDPH;
                const uint2 q = *(const uint2*)(rp);              // h0..h3
                const __half2 h01 = *(const __half2*)&q.x;
                const __half2 h23 = *(const __half2*)&q.y;
                const __half2 h45 = *(const __half2*)(rp + 4);    // h4,h5
                const float2 e0 = __half22float2(h01);
                const float2 e1 = __half22float2(h23);
                const float2 e2 = __half22float2(h45);
                const ull P0 = pack2(e0.x, e0.y);
                const ull P1 = pack2(e0.y, e1.x);
                const ull P2 = pack2(e1.x, e1.y);
                const ull P3 = pack2(e1.y, e2.x);
                const ull P4 = pack2(e2.x, e2.y);

                const ulonglong2 wv0 = *(const ulonglong2*)&s_wdup[((ky*3+0)*16 + c)*4];
                const ulonglong2 wv1 = *(const ulonglong2*)&s_wdup[((ky*3+1)*16 + c)*4];
                const ulonglong2 wv2 = *(const ulonglong2*)&s_wdup[((ky*3+2)*16 + c)*4];
                ffma2(ady0, P0, wv0.x); ffma2(ady1, P2, wv0.x);
                ffma2(adx0, P0, wv0.y); ffma2(adx1, P2, wv0.y);
                ffma2(ady0, P1, wv1.x); ffma2(ady1, P3, wv1.x);
                ffma2(adx0, P1, wv1.y); ffma2(adx1, P3, wv1.y);
                ffma2(ady0, P2, wv2.x); ffma2(ady1, P4, wv2.x);
                ffma2(adx0, P2, wv2.y); ffma2(adx1, P4, wv2.y);
            }
        }

        float dyv[4], dxv[4];
        unpack2(ady0, dyv[0], dyv[1]); unpack2(ady1, dyv[2], dyv[3]);
        unpack2(adx0, dxv[0], dxv[1]); unpack2(adx1, dxv[2], dxv[3]);

        #pragma unroll
        for (int i = 0; i < 4; i++) {
            const int gy = ty0 + row;
            const int gx = tx0 + x0p + i;
            const float py = (float)(gy + kdy) + dyv[i];
            const float px = (float)(gx + kdx) + dxv[i];
            const float y0f = floorf(py), x0f = floorf(px);
            const float wy = py - y0f, wx = px - x0f;
            const int yy0 = (int)y0f, xx0 = (int)x0f;
            const int yy1 = yy0 + 1,  xx1 = xx0 + 1;
            const bool okY0 = (yy0 >= 0) & (yy0 < Hn);
            const bool okY1 = (yy1 >= 0) & (yy1 < Hn);
            const bool okX0 = (xx0 >= 0) & (xx0 < Wn);
            const bool okX1 = (xx1 >= 0) & (xx1 < Wn);
            const float v00 = (okY0 & okX0) ? __ldg(img + (size_t)yy0*Wn + xx0) : 0.f;
            const float v01 = (okY0 & okX1) ? __ldg(img + (size_t)yy0*Wn + xx1) : 0.f;
            const float v10 = (okY1 & okX0) ? __ldg(img + (size_t)yy1*Wn + xx0) : 0.f;
            const float v11 = (okY1 & okX1) ? __ldg(img + (size_t)yy1*Wn + xx1) : 0.f;
            const float s = v00*(1.f - wy)*(1.f - wx) + v01*(1.f - wy)*wx
                          + v10*wy*(1.f - wx)         + v11*wy*wx;
            acc[i] = fmaf(wkv, s, acc[i]);
        }
    }

    float4 o4; o4.x = acc[0]; o4.y = acc[1]; o4.z = acc[2]; o4.w = acc[3];
    *(float4*)&out[(size_t)b * Hn * Wn + (size_t)(ty0 + row) * Wn + (tx0 + x0p)] = o4;
}

extern "C" void kernel_launch(void* const* d_in, const int* in_sizes, int n_in,
                              void* d_out, int out_size)
{
    const float* pm25 = (const float*)d_in[0];
    const float* wind = (const float*)d_in[1];
    const float* topo = (const float*)d_in[2];
    const float* w1   = (const float*)d_in[3];
    const float* b1   = (const float*)d_in[4];
    const float* w2   = (const float*)d_in[5];
    const float* b2   = (const float*)d_in[6];
    const float* wk   = (const float*)d_in[7];
    float* out = (float*)d_out;

    const size_t smem_bytes = (size_t)SMEM_FLOATS * sizeof(float);
    cudaFuncSetAttribute(fused_residual_advection,
                         cudaFuncAttributeMaxDynamicSharedMemorySize,
                         (int)smem_bytes);

    dim3 grid(Wn / TILE, Hn / TILE, Bn);
    fused_residual_advection<<<grid, 256, smem_bytes>>>(
        pm25, wind, topo, w1, b1, w2, b2, wk, out);
}